// round 15
// baseline (speedup 1.0000x reference)
#include <cuda_runtime.h>
#include <math.h>

#define MAX_TRI 512
#define WSTRIDE 33      // odd stride -> conflict-free scalar weight reads
#define THREADS 256
#define FSLOTS  3       // fixed slots cover j < jbase + qrem

__device__ float        g_cw[MAX_TRI * WSTRIDE];
__device__ int          g_lo[MAX_TRI];      // even-aligned band start
__device__ int          g_len[MAX_TRI];     // padded band length (mult of 4, <=32)
__device__ unsigned int g_done;             // monotonic across replays

// ---------------------------------------------------------------------------
__device__ __forceinline__ void cp_async16(float4* sptr, const float4* gptr)
{
    unsigned s = (unsigned)__cvta_generic_to_shared(sptr);
    asm volatile("cp.async.cg.shared.global [%0], [%1], 16;\n" :: "r"(s), "l"(gptr));
}
#define CP_COMMIT()  asm volatile("cp.async.commit_group;\n" ::)
#define CP_WAIT1()   asm volatile("cp.async.wait_group 1;\n" ::)
#define CP_WAIT0()   asm volatile("cp.async.wait_group 0;\n" ::)

__device__ __forceinline__ float cubic_eval(const float* xs, int i0, float f)
{
    float xm = xs[i0 - 1], c0 = xs[i0], c1 = xs[i0 + 1], c2 = xs[i0 + 2];
    return c0 + 0.5f * f * (c1 - xm +
           f * (2.f * xm - 5.f * c0 + 4.f * c1 - c2 +
           f * (3.f * (c0 - c1) + c2 - xm)));
}

// ---------------------------------------------------------------------------
// Single fused kernel: band compaction (one band per block) + spin gate +
// R8 main loop (persistent; 4 same-shift rows/pass; double-buffered 16B
// cp.async; float2 tri reads; reversed-consecutive tri map).
// ---------------------------------------------------------------------------
__global__ void __launch_bounds__(THREADS, 2)
logscale_kernel(const float* __restrict__ x,
                const float* __restrict__ flin,
                const float* __restrict__ fcub,
                const float* __restrict__ w,
                const int*   __restrict__ pidx,
                float*       __restrict__ out,
                int n_rows, int n_in, int n_lin, int n_cub, int n_tri,
                int xpitch, int n_items)
{
    extern __shared__ float smem[];
    __shared__ int s_lo, s_hi;
    const int n_out = n_lin + n_cub + n_tri;
    const int jbase = n_lin + n_cub;
    const int wtot  = n_tri * WSTRIDE;
    const int bufoff = (wtot + 3) & ~3;
    float* sw   = smem;
    float* bufs = smem + bufoff;            // 2 buffers x 4 rows x xpitch

    const int tid = threadIdx.x;
    const int N16 = (n_in + 6) >> 2;        // float4 count per staged row

    // ---- Phase 0: compact this block's band(s) into g_cw ---------------
    int myc = 0;
    for (int j = blockIdx.x; j < n_tri; j += gridDim.x) {
        if (tid == 0) { s_lo = n_in; s_hi = 0; }
        __syncthreads();
        const float* row = w + (size_t)j * n_in;
        int lo = n_in, hi = 0;
        for (int c = tid; c < n_in; c += THREADS) {
            float v = row[c];
            if (v > -1e30f) { lo = min(lo, c); hi = max(hi, c); }
        }
        atomicMin(&s_lo, lo);
        atomicMax(&s_hi, hi);
        __syncthreads();
        const int lof = s_lo, hif = s_hi;
        const int L = lof & ~1;             // even-aligned start
        int len = hif - L + 1;
        if (len > 32) len = 32;             // safety clamp (actual max ~30)
        const int lenp = (len + 3) & ~3;    // padded, mult of 4
        if (tid == 0) { g_lo[j] = L; g_len[j] = lenp; }
        for (int k = tid; k < WSTRIDE; k += THREADS) {
            int bin = L + k;
            g_cw[j * WSTRIDE + k] =
                (k < len && bin >= lof && bin <= hif) ? row[bin] : -INFINITY;
        }
        myc++;
        __syncthreads();
    }
    __threadfence();
    if (tid == 0 && myc > 0) atomicAdd(&g_done, (unsigned)myc);

    // ---- prologue x prefetch (independent of weights) -------------------
    const int stride = gridDim.x;
    auto stage = [&](int m, float* dst) {
        const int g = m >> 2, c = m & 3;
        const int rbase = 16 * g + c;
        #pragma unroll
        for (int i = 0; i < 4; i++) {
            int r = rbase + 4 * i;
            if (r >= n_rows) r = (rbase < n_rows) ? rbase : c;  // same residue
            const float4* src = (const float4*)(x + (size_t)r * n_in - c);
            float4* d4 = (float4*)(dst + i * xpitch);
            for (int t = tid; t < N16; t += THREADS) cp_async16(&d4[t], &src[t]);
        }
    };
    int m = blockIdx.x;
    if (m < n_items) stage(m, bufs);
    CP_COMMIT();

    // Zero never-staged tails (overlaps with gate/prefetch latency).
    for (int b = 0; b < 8; b++)
        for (int i = 4 * N16 + tid; i < xpitch; i += THREADS)
            bufs[b * xpitch + i] = 0.f;

    // Fixed slots 0..1 lin/cubic (independent of band metadata).
    int   kind[FSLOTS], ia[FSLOTS], ib[FSLOTS];
    float ff[FSLOTS];
    #pragma unroll
    for (int s = 0; s < FSLOTS; s++) {
        const int j = tid + s * THREADS;
        kind[s] = 3; ia[s] = 0; ib[s] = 0; ff[s] = 0.f;
        if (j < n_lin) {
            kind[s] = 0;
            ia[s] = pidx[j];
            ib[s] = pidx[j + n_lin];
            ff[s] = flin[j];
        } else if (j < jbase) {
            kind[s] = 1;
            float fc = fcub[j - n_lin];
            int i0 = (int)floorf(fc);
            ia[s] = i0;
            ff[s] = fc - (float)i0;
        }
    }

    // ---- gate: all bands compacted (first call only; replays fall through)
    if (tid == 0) {
        while (*((volatile unsigned int*)&g_done) < (unsigned)n_tri)
            __nanosleep(40);
    }
    __syncthreads();
    __threadfence();

    // Stage weights into smem; tri slot params.
    for (int i = tid; i < wtot; i += THREADS) sw[i] = g_cw[i];

    const int qrem = (n_tri > 256) ? (n_tri - 256) : 0;
    const int q3 = n_tri - 1 - tid;         // reversed-consecutive map
    const bool has3 = (q3 >= qrem);
    int lo3 = 0, lp3 = 0, wo3 = 0, j3 = 0;
    if (has3) {
        lo3 = g_lo[q3]; lp3 = g_len[q3]; wo3 = q3 * WSTRIDE; j3 = jbase + q3;
    }
    #pragma unroll
    for (int s = 0; s < FSLOTS; s++) {
        const int j = tid + s * THREADS;
        if (kind[s] == 3 && j >= jbase && j < jbase + qrem) {
            kind[s] = 2;
            const int q = j - jbase;
            ia[s] = g_lo[q]; ib[s] = g_len[q];
        }
    }
    __syncthreads();

    // ---- main loop ------------------------------------------------------
    int it = 0;
    for (; m < n_items; m += stride, it++) {
        float* cur  = bufs + (it & 1) * (4 * xpitch);
        float* nbuf = bufs + ((it + 1) & 1) * (4 * xpitch);

        const int nxt = m + stride;
        if (nxt < n_items) { stage(nxt, nbuf); CP_COMMIT(); CP_WAIT1(); }
        else               { CP_WAIT0(); }
        __syncthreads();

        const int g = m >> 2, c = m & 3;
        const int rbase = 16 * g + c;
        const float* xr0 = cur + c;
        const float* xr1 = cur + xpitch + c;
        const float* xr2 = cur + 2 * xpitch + c;
        const float* xr3 = cur + 3 * xpitch + c;
        const bool w0 = (rbase      < n_rows);
        const bool w1 = (rbase + 4  < n_rows);
        const bool w2 = (rbase + 8  < n_rows);
        const bool w3 = (rbase + 12 < n_rows);
        float* o0 = out + (size_t)rbase * n_out;
        float* o1 = o0 + (size_t)4  * n_out;
        float* o2 = o0 + (size_t)8  * n_out;
        float* o3 = o0 + (size_t)12 * n_out;
        const int pi = c & 1;

        auto tri4 = [&](int lo, int lenp, int wo, int j) {
            float m0 = -INFINITY, m1 = -INFINITY, m2 = -INFINITY, m3 = -INFINITY;
            if (pi) {
                const float wv = sw[wo];
                m0 = xr0[lo] + wv; m1 = xr1[lo] + wv;
                m2 = xr2[lo] + wv; m3 = xr3[lo] + wv;
            }
            const float2* p0 = (const float2*)(xr0 + lo + pi);
            const float2* p1 = (const float2*)(xr1 + lo + pi);
            const float2* p2 = (const float2*)(xr2 + lo + pi);
            const float2* p3 = (const float2*)(xr3 + lo + pi);
            const float*  wp = sw + wo + pi;
            const int half = lenp >> 1;
            #pragma unroll 2
            for (int t = 0; t < half; t++) {
                const float wa = wp[2 * t], wb = wp[2 * t + 1];
                float2 v;
                v = p0[t]; m0 = fmaxf(m0, v.x + wa); m0 = fmaxf(m0, v.y + wb);
                v = p1[t]; m1 = fmaxf(m1, v.x + wa); m1 = fmaxf(m1, v.y + wb);
                v = p2[t]; m2 = fmaxf(m2, v.x + wa); m2 = fmaxf(m2, v.y + wb);
                v = p3[t]; m3 = fmaxf(m3, v.x + wa); m3 = fmaxf(m3, v.y + wb);
            }
            if (w0) o0[j] = m0;
            if (w1) o1[j] = m1;
            if (w2) o2[j] = m2;
            if (w3) o3[j] = m3;
        };

        #pragma unroll
        for (int s = 0; s < FSLOTS; s++) {
            if (kind[s] == 3) continue;
            const int j = tid + s * THREADS;
            if (kind[s] == 2) { tri4(ia[s], ib[s], (j - jbase) * WSTRIDE, j); continue; }
            float v0, v1, v2, v3;
            if (kind[s] == 0) {
                const int a = ia[s], b = ib[s];
                const float f = ff[s];
                float a0 = xr0[a], b0 = xr0[b]; v0 = a0 + f * (b0 - a0);
                float a1 = xr1[a], b1 = xr1[b]; v1 = a1 + f * (b1 - a1);
                float a2 = xr2[a], b2 = xr2[b]; v2 = a2 + f * (b2 - a2);
                float a3 = xr3[a], b3 = xr3[b]; v3 = a3 + f * (b3 - a3);
            } else {
                const int i0 = ia[s];
                const float f = ff[s];
                v0 = cubic_eval(xr0, i0, f);
                v1 = cubic_eval(xr1, i0, f);
                v2 = cubic_eval(xr2, i0, f);
                v3 = cubic_eval(xr3, i0, f);
            }
            if (w0) o0[j] = v0;
            if (w1) o1[j] = v1;
            if (w2) o2[j] = v2;
            if (w3) o3[j] = v3;
        }

        if (has3) tri4(lo3, lp3, wo3, j3);

        __syncthreads();
    }
}

// ---------------------------------------------------------------------------
extern "C" void kernel_launch(void* const* d_in, const int* in_sizes, int n_in_arr,
                              void* d_out, int out_size)
{
    const float* x    = (const float*)d_in[0];
    const float* flin = (const float*)d_in[1];
    const float* fcub = (const float*)d_in[2];
    const float* w    = (const float*)d_in[3];
    const int*   pidx = (const int*)d_in[4];

    const int n_lin = in_sizes[1];
    const int n_cub = in_sizes[2];

    // Solve (n_tri, n_in, n_rows) from the size system; unique factorization.
    int n_tri = 0, N_IN = 0, n_rows = 0;
    for (int t = 1; t <= MAX_TRI; t++) {
        if (in_sizes[3] % t) continue;
        long ni = in_sizes[3] / t;
        if (ni <= 0 || (long)in_sizes[0] % ni) continue;
        long rows = (long)in_sizes[0] / ni;
        if (rows * (long)(n_lin + n_cub + t) == (long)out_size) {
            n_tri = t; N_IN = (int)ni; n_rows = (int)rows;
            break;
        }
    }
    if (n_tri == 0) return;

    const int N16    = (N_IN + 6) >> 2;
    const int xpitch = 4 * N16 + 8;                       // staged + pad, mult of 4
    const int bufoff = (n_tri * WSTRIDE + 3) & ~3;
    const int smem_bytes = (bufoff + 8 * xpitch) * (int)sizeof(float);
    cudaFuncSetAttribute(logscale_kernel,
                         cudaFuncAttributeMaxDynamicSharedMemorySize, smem_bytes);

    const int n_items = 4 * ((n_rows + 15) / 16);         // 4 rows per item
    int grid = 148 * 2;                                   // persistent, all resident
    if (grid > n_items) grid = n_items;
    if (grid < 1) grid = 1;

    logscale_kernel<<<grid, THREADS, smem_bytes>>>(
        x, flin, fcub, w, pidx, (float*)d_out,
        n_rows, N_IN, n_lin, n_cub, n_tri, xpitch, n_items);
}

// round 17
// speedup vs baseline: 1.5010x; 1.5010x over previous
#include <cuda_runtime.h>
#include <cstdint>
#include <math.h>

#define MAX_TRI 512
#define WSTRIDE 33      // odd stride -> conflict-free scalar weight reads
#define THREADS 256
#define FSLOTS  3       // fixed slots cover j < jbase + qrem

__device__ float g_cw[MAX_TRI * WSTRIDE];
__device__ int   g_lo[MAX_TRI];     // even-aligned band start
__device__ int   g_len[MAX_TRI];    // padded band length (mult of 4, <=32)

// ---------------------------------------------------------------------------
// mbarrier + bulk-async helpers
// ---------------------------------------------------------------------------
__device__ __forceinline__ uint32_t smem_u32(const void* p)
{
    return (uint32_t)__cvta_generic_to_shared(p);
}
__device__ __forceinline__ void mbar_init(uint32_t mbar, uint32_t count)
{
    asm volatile("mbarrier.init.shared.b64 [%0], %1;" :: "r"(mbar), "r"(count) : "memory");
}
__device__ __forceinline__ void mbar_expect_tx(uint32_t mbar, uint32_t bytes)
{
    asm volatile("mbarrier.arrive.expect_tx.shared.b64 _, [%0], %1;"
                 :: "r"(mbar), "r"(bytes) : "memory");
}
__device__ __forceinline__ void bulk_g2s(uint32_t dst, const void* src,
                                         uint32_t bytes, uint32_t mbar)
{
    asm volatile("cp.async.bulk.shared::cluster.global.mbarrier::complete_tx::bytes "
                 "[%0], [%1], %2, [%3];"
                 :: "r"(dst), "l"(src), "r"(bytes), "r"(mbar) : "memory");
}
__device__ __forceinline__ void mbar_wait(uint32_t mbar, uint32_t parity)
{
    asm volatile(
        "{\n\t"
        ".reg .pred P;\n\t"
        "WAIT_%=:\n\t"
        "mbarrier.try_wait.parity.acquire.cta.shared::cta.b64 P, [%0], %1, 0x989680;\n\t"
        "@P bra.uni DONE_%=;\n\t"
        "bra.uni WAIT_%=;\n\t"
        "DONE_%=:\n\t"
        "}"
        :: "r"(mbar), "r"(parity) : "memory");
}

// ---------------------------------------------------------------------------
// Preprocess: compact the finite band of each triangular-weight row.
// ---------------------------------------------------------------------------
__global__ void prep_kernel(const float* __restrict__ w, int n_tri, int n_in)
{
    int j = blockIdx.x;
    if (j >= n_tri) return;
    __shared__ int s_lo, s_hi;
    if (threadIdx.x == 0) { s_lo = n_in; s_hi = 0; }
    __syncthreads();

    const float* row = w + (size_t)j * n_in;
    int lo = n_in, hi = 0;
    const int n4 = n_in >> 2;
    if ((((size_t)row) & 15) == 0) {
        const float4* row4 = (const float4*)row;
        for (int c4 = threadIdx.x; c4 < n4; c4 += blockDim.x) {
            float4 v = row4[c4];
            int c = c4 << 2;
            if (v.x > -1e30f) { lo = min(lo, c);     hi = max(hi, c);     }
            if (v.y > -1e30f) { lo = min(lo, c + 1); hi = max(hi, c + 1); }
            if (v.z > -1e30f) { lo = min(lo, c + 2); hi = max(hi, c + 2); }
            if (v.w > -1e30f) { lo = min(lo, c + 3); hi = max(hi, c + 3); }
        }
        for (int c = (n4 << 2) + threadIdx.x; c < n_in; c += blockDim.x) {
            float v = row[c];
            if (v > -1e30f) { lo = min(lo, c); hi = max(hi, c); }
        }
    } else {
        for (int c = threadIdx.x; c < n_in; c += blockDim.x) {
            float v = row[c];
            if (v > -1e30f) { lo = min(lo, c); hi = max(hi, c); }
        }
    }
    atomicMin(&s_lo, lo);
    atomicMax(&s_hi, hi);
    __syncthreads();

    const int lof = s_lo, hif = s_hi;
    const int L = lof & ~1;             // even-aligned start
    int len = hif - L + 1;
    if (len > 32) len = 32;             // safety clamp (actual max ~30)
    const int lenp = (len + 3) & ~3;
    if (threadIdx.x == 0) { g_lo[j] = L; g_len[j] = lenp; }
    for (int k = threadIdx.x; k < WSTRIDE; k += blockDim.x) {
        int bin = L + k;
        g_cw[j * WSTRIDE + k] =
            (k < len && bin >= lof && bin <= hif) ? row[bin] : -INFINITY;
    }
}

__device__ __forceinline__ float cubic_eval(const float* xs, int i0, float f)
{
    float xm = xs[i0 - 1], c0 = xs[i0], c1 = xs[i0 + 1], c2 = xs[i0 + 2];
    return c0 + 0.5f * f * (c1 - xm +
           f * (2.f * xm - 5.f * c0 + 4.f * c1 - c2 +
           f * (3.f * (c0 - c1) + c2 - xm)));
}

// ---------------------------------------------------------------------------
// Main kernel: persistent blocks; 4 same-shift rows per pass; bulk-async
// (TMA path) double-buffered staging via mbarrier complete_tx; float2 tri
// reads; reversed-consecutive tri map (R8).
// ---------------------------------------------------------------------------
__global__ void __launch_bounds__(THREADS, 2)
logscale_kernel(const float* __restrict__ x,
                const float* __restrict__ flin,
                const float* __restrict__ fcub,
                const int*   __restrict__ pidx,
                float*       __restrict__ out,
                int n_rows, int n_in, int n_lin, int n_cub, int n_tri,
                int xpitch, int n_items)
{
    extern __shared__ float smem[];
    const int n_out = n_lin + n_cub + n_tri;
    const int jbase = n_lin + n_cub;
    const int wtot  = n_tri * WSTRIDE;

    // Layout: [0..4) mbarriers (2 x u64, 16B), [4..) weights, then buffers.
    unsigned long long* mbars = (unsigned long long*)smem;
    float* sw   = smem + 4;
    const int bufoff = 4 + ((wtot + 3) & ~3);
    float* bufs = smem + bufoff;            // 2 buffers x 4 rows x xpitch
    const uint32_t bar0 = smem_u32(&mbars[0]);
    const uint32_t bar1 = smem_u32(&mbars[1]);

    const int tid = threadIdx.x;
    const int N16 = (n_in + 6) >> 2;        // float4 count per staged row
    const uint32_t row_bytes = (uint32_t)N16 * 16u;
    const uint32_t bufs_u32  = smem_u32(bufs);

    if (tid == 0) { mbar_init(bar0, 1); mbar_init(bar1, 1); }

    // Stage weights into shared memory (once per block lifetime).
    for (int i = tid; i < wtot; i += THREADS) sw[i] = g_cw[i];

    // Zero never-staged tails of all 8 row buffers.
    for (int b = 0; b < 8; b++)
        for (int i = 4 * N16 + tid; i < xpitch; i += THREADS)
            bufs[b * xpitch + i] = 0.f;

    // Tri assignment (R8): shortest bands via slot 2 identity, rest reversed.
    const int qrem = (n_tri > 256) ? (n_tri - 256) : 0;
    const int q3 = n_tri - 1 - tid;
    const bool has3 = (q3 >= qrem);
    int lo3 = 0, lp3 = 0, wo3 = 0, j3 = 0;
    if (has3) {
        lo3 = g_lo[q3]; lp3 = g_len[q3]; wo3 = q3 * WSTRIDE; j3 = jbase + q3;
    }

    int   kind[FSLOTS], ia[FSLOTS], ib[FSLOTS];
    float ff[FSLOTS];
    #pragma unroll
    for (int s = 0; s < FSLOTS; s++) {
        const int j = tid + s * THREADS;
        kind[s] = 3; ia[s] = 0; ib[s] = 0; ff[s] = 0.f;
        if (j < n_lin) {
            kind[s] = 0;
            ia[s] = pidx[j];
            ib[s] = pidx[j + n_lin];
            ff[s] = flin[j];
        } else if (j < jbase) {
            kind[s] = 1;
            float fc = fcub[j - n_lin];
            int i0 = (int)floorf(fc);
            ia[s] = i0;
            ff[s] = fc - (float)i0;
        } else if (j < jbase + qrem) {
            kind[s] = 2;
            const int q = j - jbase;
            ia[s] = g_lo[q]; ib[s] = g_len[q];
        }
    }
    __syncthreads();        // mbarrier init + smem zeroing visible to all

    const int stride = gridDim.x;

    // Issue 4 bulk copies for item m into buffer b (tid 0 only).
    auto stage = [&](int m, int b, uint32_t bar) {
        if (tid != 0) return;
        const int g = m >> 2, c = m & 3;
        const int rbase = 16 * g + c;
        mbar_expect_tx(bar, 4u * row_bytes);
        #pragma unroll
        for (int i = 0; i < 4; i++) {
            int r = rbase + 4 * i;
            if (r >= n_rows) r = (rbase < n_rows) ? rbase : c;  // same residue
            const void* src = (const void*)(x + (size_t)r * n_in - c);
            uint32_t dst = bufs_u32 + (uint32_t)((b * 4 + i) * xpitch) * 4u;
            bulk_g2s(dst, src, row_bytes, bar);
        }
    };

    int m = blockIdx.x;
    if (m < n_items) stage(m, 0, bar0);

    int it = 0;
    for (; m < n_items; m += stride, it++) {
        const int b = it & 1;
        float* cur = bufs + b * (4 * xpitch);

        const int nxt = m + stride;
        if (nxt < n_items) stage(nxt, 1 - b, b ? bar0 : bar1);

        mbar_wait(b ? bar1 : bar0, (uint32_t)((it >> 1) & 1));

        const int g = m >> 2, c = m & 3;
        const int rbase = 16 * g + c;
        const float* xr0 = cur + c;
        const float* xr1 = cur + xpitch + c;
        const float* xr2 = cur + 2 * xpitch + c;
        const float* xr3 = cur + 3 * xpitch + c;
        const bool w0 = (rbase      < n_rows);
        const bool w1 = (rbase + 4  < n_rows);
        const bool w2 = (rbase + 8  < n_rows);
        const bool w3 = (rbase + 12 < n_rows);
        float* o0 = out + (size_t)rbase * n_out;
        float* o1 = o0 + (size_t)4  * n_out;
        float* o2 = o0 + (size_t)8  * n_out;
        float* o3 = o0 + (size_t)12 * n_out;
        const int pi = c & 1;

        auto tri4 = [&](int lo, int lenp, int wo, int j) {
            float m0 = -INFINITY, m1 = -INFINITY, m2 = -INFINITY, m3 = -INFINITY;
            if (pi) {
                const float wv = sw[wo];
                m0 = xr0[lo] + wv; m1 = xr1[lo] + wv;
                m2 = xr2[lo] + wv; m3 = xr3[lo] + wv;
            }
            const float2* p0 = (const float2*)(xr0 + lo + pi);
            const float2* p1 = (const float2*)(xr1 + lo + pi);
            const float2* p2 = (const float2*)(xr2 + lo + pi);
            const float2* p3 = (const float2*)(xr3 + lo + pi);
            const float*  wp = sw + wo + pi;
            const int half = lenp >> 1;
            #pragma unroll 2
            for (int t = 0; t < half; t++) {
                const float wa = wp[2 * t], wb = wp[2 * t + 1];
                float2 v;
                v = p0[t]; m0 = fmaxf(m0, v.x + wa); m0 = fmaxf(m0, v.y + wb);
                v = p1[t]; m1 = fmaxf(m1, v.x + wa); m1 = fmaxf(m1, v.y + wb);
                v = p2[t]; m2 = fmaxf(m2, v.x + wa); m2 = fmaxf(m2, v.y + wb);
                v = p3[t]; m3 = fmaxf(m3, v.x + wa); m3 = fmaxf(m3, v.y + wb);
            }
            if (w0) o0[j] = m0;
            if (w1) o1[j] = m1;
            if (w2) o2[j] = m2;
            if (w3) o3[j] = m3;
        };

        #pragma unroll
        for (int s = 0; s < FSLOTS; s++) {
            if (kind[s] == 3) continue;
            const int j = tid + s * THREADS;
            if (kind[s] == 2) { tri4(ia[s], ib[s], (j - jbase) * WSTRIDE, j); continue; }
            float v0, v1, v2, v3;
            if (kind[s] == 0) {
                const int a = ia[s], b2 = ib[s];
                const float f = ff[s];
                float a0 = xr0[a], b0 = xr0[b2]; v0 = a0 + f * (b0 - a0);
                float a1 = xr1[a], b1 = xr1[b2]; v1 = a1 + f * (b1 - a1);
                float a2 = xr2[a], c2 = xr2[b2]; v2 = a2 + f * (c2 - a2);
                float a3 = xr3[a], b3 = xr3[b2]; v3 = a3 + f * (b3 - a3);
            } else {
                const int i0 = ia[s];
                const float f = ff[s];
                v0 = cubic_eval(xr0, i0, f);
                v1 = cubic_eval(xr1, i0, f);
                v2 = cubic_eval(xr2, i0, f);
                v3 = cubic_eval(xr3, i0, f);
            }
            if (w0) o0[j] = v0;
            if (w1) o1[j] = v1;
            if (w2) o2[j] = v2;
            if (w3) o3[j] = v3;
        }

        if (has3) tri4(lo3, lp3, wo3, j3);

        __syncthreads();    // all reads of cur done before it is re-staged
    }
}

// ---------------------------------------------------------------------------
extern "C" void kernel_launch(void* const* d_in, const int* in_sizes, int n_in_arr,
                              void* d_out, int out_size)
{
    const float* x    = (const float*)d_in[0];
    const float* flin = (const float*)d_in[1];
    const float* fcub = (const float*)d_in[2];
    const float* w    = (const float*)d_in[3];
    const int*   pidx = (const int*)d_in[4];

    const int n_lin = in_sizes[1];
    const int n_cub = in_sizes[2];

    // Solve (n_tri, n_in, n_rows) from the size system; unique factorization.
    int n_tri = 0, N_IN = 0, n_rows = 0;
    for (int t = 1; t <= MAX_TRI; t++) {
        if (in_sizes[3] % t) continue;
        long ni = in_sizes[3] / t;
        if (ni <= 0 || (long)in_sizes[0] % ni) continue;
        long rows = (long)in_sizes[0] / ni;
        if (rows * (long)(n_lin + n_cub + t) == (long)out_size) {
            n_tri = t; N_IN = (int)ni; n_rows = (int)rows;
            break;
        }
    }
    if (n_tri == 0) return;

    prep_kernel<<<n_tri, 256>>>(w, n_tri, N_IN);

    const int N16    = (N_IN + 6) >> 2;
    const int xpitch = 4 * N16 + 8;                       // staged + pad, mult of 4
    const int bufoff = 4 + ((n_tri * WSTRIDE + 3) & ~3);  // mbarriers + weights
    const int smem_bytes = (bufoff + 8 * xpitch) * (int)sizeof(float);
    cudaFuncSetAttribute(logscale_kernel,
                         cudaFuncAttributeMaxDynamicSharedMemorySize, smem_bytes);

    const int n_items = 4 * ((n_rows + 15) / 16);         // 4 rows per item
    int grid = 148 * 2;                                   // persistent: 2 blocks / SM
    if (grid > n_items) grid = n_items;

    logscale_kernel<<<grid, THREADS, smem_bytes>>>(
        x, flin, fcub, pidx, (float*)d_out,
        n_rows, N_IN, n_lin, n_cub, n_tri, xpitch, n_items);
}